// round 3
// baseline (speedup 1.0000x reference)
#include <cuda_runtime.h>
#include <cstdint>
#include <math.h>

#define DIM 256
#define HID 512
#define NMAXN 100352
#define EMAXE 401408
#define ASTRIDE 20
#define KC 16

// ---------------- device scratch (allocation-free) ----------------
__device__ float g_h  [(size_t)NMAXN * DIM];
__device__ float g_agg[(size_t)NMAXN * DIM];
__device__ float g_hid[(size_t)NMAXN * HID];
__device__ float g_Wtl[256 * 128];            // Wl^T  [N=256][K=128]
__device__ float g_Wt1[5 * 512 * 256];        // W1^T  [l][N=512][K=256]
__device__ float g_Wt2[5 * 256 * 512];        // W2^T  [l][N=256][K=512]
__device__ int   g_deg [NMAXN];
__device__ int   g_rp  [NMAXN + 1];
__device__ int   g_cur [NMAXN];
__device__ int   g_csr [EMAXE];
__device__ int   g_cntT[NMAXN * 6];
__device__ int   g_cntD[NMAXN * 3];
__device__ int   g_bsum[600];
__device__ float g_bnsum[DIM];
__device__ float g_bnsq [DIM];
__device__ float g_scale[DIM];
__device__ float g_shift[DIM];

// ---------------- helpers ----------------
__device__ __forceinline__ uint32_t smem_u32(const void* p) {
    uint32_t a;
    asm("{ .reg .u64 t; cvta.to.shared.u64 t, %1; cvt.u32.u64 %0, t; }" : "=r"(a) : "l"(p));
    return a;
}
#define CPA16(dst, src) \
    asm volatile("cp.async.cg.shared.global [%0], [%1], 16;" :: "r"(dst), "l"(src))
#define CP_COMMIT() asm volatile("cp.async.commit_group;")
#define CP_WAIT0()  asm volatile("cp.async.wait_group 0;")
#define CP_WAIT1()  asm volatile("cp.async.wait_group 1;")

__device__ __forceinline__ void mma8(float* c, const uint32_t* a, const uint32_t* b) {
    asm volatile("mma.sync.aligned.m16n8k8.row.col.f32.tf32.tf32.f32 "
        "{%0,%1,%2,%3}, {%4,%5,%6,%7}, {%8,%9}, {%0,%1,%2,%3};"
        : "+f"(c[0]), "+f"(c[1]), "+f"(c[2]), "+f"(c[3])
        : "r"(a[0]), "r"(a[1]), "r"(a[2]), "r"(a[3]), "r"(b[0]), "r"(b[1]));
}
__device__ __forceinline__ void split(float x, uint32_t& hi, uint32_t& lo) {
    uint32_t h = __float_as_uint(x) & 0xFFFFE000u;
    hi = h;
    float l = x - __uint_as_float(h);
    lo = __float_as_uint(l) & 0xFFFFE000u;
}

// ---------------- weight transpose: Wt[l][n][k] = W[l][k][n] ----------------
__global__ void k_transpose(const float* __restrict__ W, float* __restrict__ Wt,
                            int K, int Nc, int L) {
    int idx = blockIdx.x * blockDim.x + threadIdx.x;
    int tot = L * K * Nc;
    if (idx < tot) {
        int l = idx / (K * Nc);
        int r = idx - l * K * Nc;
        int k = r / Nc;
        int n = r - k * Nc;
        Wt[((size_t)l * Nc + n) * K + k] = W[idx];
    }
}

// ---------------- setup kernels (CSR + edge-type counts) ----------------
__global__ void k_zero_counts(int n) {
    int i = blockIdx.x * blockDim.x + threadIdx.x;
    if (i < n) {
        g_deg[i] = 0;
#pragma unroll
        for (int t = 0; t < 6; t++) g_cntT[i * 6 + t] = 0;
#pragma unroll
        for (int d = 0; d < 3; d++) g_cntD[i * 3 + d] = 0;
    }
}
__global__ void k_zero_bn() {
    int i = threadIdx.x;
    if (i < DIM) { g_bnsum[i] = 0.f; g_bnsq[i] = 0.f; }
}
__global__ void k_count(const int* __restrict__ ei, const int* __restrict__ ea, int E) {
    int e = blockIdx.x * blockDim.x + threadIdx.x;
    if (e < E) {
        int d = ei[E + e];
        atomicAdd(&g_deg[d], 1);
        int bt = ea[2 * e], bd = ea[2 * e + 1];
        if ((unsigned)bt < 6u) atomicAdd(&g_cntT[d * 6 + bt], 1);
        if ((unsigned)bd < 3u) atomicAdd(&g_cntD[d * 3 + bd], 1);
    }
}
__global__ void k_scan1(int n) {
    __shared__ int s[512];
    int tid = threadIdx.x, i = blockIdx.x * 512 + tid;
    int v = (i < n) ? g_deg[i] : 0;
    s[tid] = v; __syncthreads();
    for (int off = 1; off < 512; off <<= 1) {
        int t = (tid >= off) ? s[tid - off] : 0;
        __syncthreads(); s[tid] += t; __syncthreads();
    }
    if (i < n) g_rp[i] = s[tid] - v;
    if (tid == 511) g_bsum[blockIdx.x] = s[511];
}
__global__ void k_scan2(int nb) {
    __shared__ int s[256];
    int tid = threadIdx.x;
    int v = (tid < nb) ? g_bsum[tid] : 0;
    s[tid] = v; __syncthreads();
    for (int off = 1; off < 256; off <<= 1) {
        int t = (tid >= off) ? s[tid - off] : 0;
        __syncthreads(); s[tid] += t; __syncthreads();
    }
    if (tid < nb) g_bsum[tid] = s[tid] - v;
    if (tid == 0) g_bsum[nb] = s[255];
}
__global__ void k_scan3(int n, int nb) {
    int i = blockIdx.x * 512 + threadIdx.x;
    if (i < n) {
        int r = g_rp[i] + g_bsum[blockIdx.x];
        g_rp[i] = r; g_cur[i] = r;
    }
    if (i == 0) g_rp[n] = g_bsum[nb];
}
__global__ void k_scatter(const int* __restrict__ ei, int E) {
    int e = blockIdx.x * blockDim.x + threadIdx.x;
    if (e < E) {
        int s = ei[e], d = ei[E + e];
        int p = atomicAdd(&g_cur[d], 1);
        g_csr[p] = s;
    }
}

// ---------------- fused BN-apply + aggregation ----------------
__device__ __forceinline__ void add4(float4& a, const float4 b) {
    a.x += b.x; a.y += b.y; a.z += b.z; a.w += b.w;
}
__device__ __forceinline__ void fma4(float4& a, float s, const float4 b) {
    a.x += s * b.x; a.y += s * b.y; a.z += s * b.z; a.w += s * b.w;
}
__global__ void k_agg(const float* __restrict__ E1l, const float* __restrict__ E2l,
                      int n, int use_bn) {
    __shared__ float sE[2560];      // E1 6x256 | E2 3x256 | self 256
    __shared__ float sSc[256], sSh[256];
    int tid = threadIdx.x;
    for (int i = tid; i < 1536; i += 256) sE[i] = E1l[i];
    for (int i = tid; i < 768; i += 256) sE[1536 + i] = E2l[i];
    if (use_bn) { sSc[tid] = g_scale[tid]; sSh[tid] = g_shift[tid]; }
    else        { sSc[tid] = 1.f;          sSh[tid] = 0.f; }
    __syncthreads();
    sE[2304 + tid] = sE[4 * 256 + tid] + sE[1536 + tid];   // E1[4]+E2[0]
    __syncthreads();

    int node = blockIdx.x * 8 + (tid >> 5);
    if (node >= n) return;
    int lane = tid & 31;
    int c0 = lane * 4, c1 = 128 + lane * 4;

    float4 b0 = *(const float4*)(sE + 2304 + c0);
    float4 b1 = *(const float4*)(sE + 2304 + c1);
#pragma unroll
    for (int t = 0; t < 6; t++) {
        int ct = g_cntT[node * 6 + t];
        if (ct) {
            float f = (float)ct;
            fma4(b0, f, *(const float4*)(sE + t * 256 + c0));
            fma4(b1, f, *(const float4*)(sE + t * 256 + c1));
        }
    }
#pragma unroll
    for (int d = 0; d < 3; d++) {
        int cd = g_cntD[node * 3 + d];
        if (cd) {
            float f = (float)cd;
            fma4(b0, f, *(const float4*)(sE + 1536 + d * 256 + c0));
            fma4(b1, f, *(const float4*)(sE + 1536 + d * 256 + c1));
        }
    }
    const float* hr = g_h + (size_t)node * DIM;
    float4 a0 = *(const float4*)(hr + c0);
    float4 a1 = *(const float4*)(hr + c1);
    int e0 = g_rp[node], e1 = g_rp[node + 1];
    for (int e = e0; e < e1; e++) {
        const float* hs = g_h + (size_t)g_csr[e] * DIM;
        add4(a0, *(const float4*)(hs + c0));
        add4(a1, *(const float4*)(hs + c1));
    }
    float degp1 = (float)(e1 - e0 + 1);
    float4 r0, r1;
    r0.x = sSc[c0+0]*a0.x + degp1*sSh[c0+0] + b0.x;
    r0.y = sSc[c0+1]*a0.y + degp1*sSh[c0+1] + b0.y;
    r0.z = sSc[c0+2]*a0.z + degp1*sSh[c0+2] + b0.z;
    r0.w = sSc[c0+3]*a0.w + degp1*sSh[c0+3] + b0.w;
    r1.x = sSc[c1+0]*a1.x + degp1*sSh[c1+0] + b1.x;
    r1.y = sSc[c1+1]*a1.y + degp1*sSh[c1+1] + b1.y;
    r1.z = sSc[c1+2]*a1.z + degp1*sSh[c1+2] + b1.z;
    r1.w = sSc[c1+3]*a1.w + degp1*sSh[c1+3] + b1.w;
    float* ar = g_agg + (size_t)node * DIM;
    *(float4*)(ar + c0) = r0;
    *(float4*)(ar + c1) = r1;
}

// ---------------- 3xTF32 mma.sync GEMM ----------------
// CTA 128x128, 8 warps (4 m x 2 n), warp tile 32x64, K chunks of 16, cp.async double buffer.
__device__ __forceinline__ void ld_chunk(float* AsB, float* BsB,
    const float* __restrict__ A, const float* __restrict__ Bt,
    int M, int K, int rowBase, int colBase, int k0, int tid)
{
#pragma unroll
    for (int i = 0; i < 2; i++) {
        int idx = i * 256 + tid;
        int row = idx >> 2, kq = (idx & 3) * 4;
        int gr = rowBase + row; if (gr > M - 1) gr = M - 1;
        CPA16(smem_u32(AsB + row * ASTRIDE + kq), A + (size_t)gr * K + k0 + kq);
    }
#pragma unroll
    for (int i = 0; i < 2; i++) {
        int idx = i * 256 + tid;
        int row = idx >> 2, kq = (idx & 3) * 4;
        CPA16(smem_u32(BsB + row * ASTRIDE + kq), Bt + (size_t)(colBase + row) * K + k0 + kq);
    }
}

__global__ void __launch_bounds__(256, 1) k_gemm_mma(
    const float* __restrict__ A, const float* __restrict__ Bt,
    const float* __restrict__ bias, float* __restrict__ C,
    int M, int K, int Nn, int NC, int relu)
{
    __shared__ __align__(16) float As[2][128 * ASTRIDE];
    __shared__ __align__(16) float Bs[2][128 * ASTRIDE];
    __shared__ float bias_s[128];

    int tid = threadIdx.x;
    int wid = tid >> 5, lane = tid & 31;
    int wm = wid & 3, wn = wid >> 2;
    int g = lane >> 2, t = lane & 3;
    int rowBase = blockIdx.y * 128, colBase = blockIdx.x * 128;

    if (tid < 128) bias_s[tid] = bias[colBase + tid];

    float c[2][8][4];
#pragma unroll
    for (int i = 0; i < 2; i++)
#pragma unroll
        for (int j = 0; j < 8; j++)
#pragma unroll
            for (int q = 0; q < 4; q++) c[i][j][q] = 0.f;

    ld_chunk(As[0], Bs[0], A, Bt, M, K, rowBase, colBase, 0, tid);
    CP_COMMIT();

    for (int ck = 0; ck < NC; ck++) {
        if (ck + 1 < NC) {
            ld_chunk(As[(ck + 1) & 1], Bs[(ck + 1) & 1], A, Bt, M, K,
                     rowBase, colBase, (ck + 1) * KC, tid);
            CP_COMMIT();
            CP_WAIT1();
        } else {
            CP_WAIT0();
        }
        __syncthreads();

        const float* Ab = As[ck & 1];
        const float* Bb = Bs[ck & 1];
#pragma unroll
        for (int s = 0; s < 2; s++) {
            int kk = s * 8;
            uint32_t ahi[2][4], alo[2][4];
#pragma unroll
            for (int mt = 0; mt < 2; mt++) {
                int r0 = wm * 32 + mt * 16 + g;
                split(Ab[r0 * ASTRIDE + kk + t],           ahi[mt][0], alo[mt][0]);
                split(Ab[(r0 + 8) * ASTRIDE + kk + t],     ahi[mt][1], alo[mt][1]);
                split(Ab[r0 * ASTRIDE + kk + t + 4],       ahi[mt][2], alo[mt][2]);
                split(Ab[(r0 + 8) * ASTRIDE + kk + t + 4], ahi[mt][3], alo[mt][3]);
            }
            uint32_t bhi[8][2], blo[8][2];
#pragma unroll
            for (int nt = 0; nt < 8; nt++) {
                int n0 = wn * 64 + nt * 8 + g;
                split(Bb[n0 * ASTRIDE + kk + t],     bhi[nt][0], blo[nt][0]);
                split(Bb[n0 * ASTRIDE + kk + t + 4], bhi[nt][1], blo[nt][1]);
            }
#pragma unroll
            for (int mt = 0; mt < 2; mt++)
#pragma unroll
                for (int nt = 0; nt < 8; nt++) mma8(c[mt][nt], ahi[mt], bhi[nt]);
#pragma unroll
            for (int mt = 0; mt < 2; mt++)
#pragma unroll
                for (int nt = 0; nt < 8; nt++) mma8(c[mt][nt], alo[mt], bhi[nt]);
#pragma unroll
            for (int mt = 0; mt < 2; mt++)
#pragma unroll
                for (int nt = 0; nt < 8; nt++) mma8(c[mt][nt], ahi[mt], blo[nt]);
        }
        __syncthreads();
    }

    // epilogue: bias (+relu), direct global stores
#pragma unroll
    for (int mt = 0; mt < 2; mt++) {
        int r0 = rowBase + wm * 32 + mt * 16 + g;
        int r1 = r0 + 8;
#pragma unroll
        for (int nt = 0; nt < 8; nt++) {
            int colL = wn * 64 + nt * 8 + 2 * t;
            float bz0 = bias_s[colL], bz1 = bias_s[colL + 1];
            float v0 = c[mt][nt][0] + bz0;
            float v1 = c[mt][nt][1] + bz1;
            float v2 = c[mt][nt][2] + bz0;
            float v3 = c[mt][nt][3] + bz1;
            if (relu) {
                v0 = fmaxf(v0, 0.f); v1 = fmaxf(v1, 0.f);
                v2 = fmaxf(v2, 0.f); v3 = fmaxf(v3, 0.f);
            }
            if (r0 < M) *(float2*)(C + (size_t)r0 * Nn + colBase + colL) = make_float2(v0, v1);
            if (r1 < M) *(float2*)(C + (size_t)r1 * Nn + colBase + colL) = make_float2(v2, v3);
        }
    }
}

// ---------------- BN statistics + finalize + final apply ----------------
__global__ void k_bnstats(const float* __restrict__ X, int n) {
    int col = threadIdx.x;
    int r0 = blockIdx.x * 512;
    int r1 = min(r0 + 512, n);
    float s = 0.f, q = 0.f;
    for (int r = r0; r < r1; r++) {
        float v = X[(size_t)r * DIM + col];
        s += v; q += v * v;
    }
    atomicAdd(&g_bnsum[col], s);
    atomicAdd(&g_bnsq[col], q);
}
__global__ void k_bnfin(const float* __restrict__ gamma, const float* __restrict__ beta, float invN) {
    int c = threadIdx.x;
    float m = g_bnsum[c] * invN;
    float var = g_bnsq[c] * invN - m * m;
    float sc = gamma[c] * rsqrtf(var + 1e-5f);
    g_scale[c] = sc;
    g_shift[c] = beta[c] - m * sc;
}
__global__ void k_bnapply(float* __restrict__ dst, int n) {
    int i = blockIdx.x * blockDim.x + threadIdx.x;
    int tot = n * 64;
    if (i < tot) {
        int c4 = (i & 63) * 4;
        float4 v = *((const float4*)g_h + i);
        v.x = v.x * g_scale[c4 + 0] + g_shift[c4 + 0];
        v.y = v.y * g_scale[c4 + 1] + g_shift[c4 + 1];
        v.z = v.z * g_scale[c4 + 2] + g_shift[c4 + 2];
        v.w = v.w * g_scale[c4 + 3] + g_shift[c4 + 3];
        *((float4*)dst + i) = v;
    }
}

// ---------------- launch ----------------
extern "C" void kernel_launch(void* const* d_in, const int* in_sizes, int n_in,
                              void* d_out, int out_size) {
    const float* x     = (const float*)d_in[0];
    const int*   ei    = (const int*)  d_in[1];
    const int*   ea    = (const int*)  d_in[2];
    const float* Wl    = (const float*)d_in[3];
    const float* bl    = (const float*)d_in[4];
    const float* W1    = (const float*)d_in[5];
    const float* b1    = (const float*)d_in[6];
    const float* W2    = (const float*)d_in[7];
    const float* b2    = (const float*)d_in[8];
    const float* E1    = (const float*)d_in[9];
    const float* E2    = (const float*)d_in[10];
    const float* gamma = (const float*)d_in[11];
    const float* beta  = (const float*)d_in[12];

    int N = in_sizes[0] / 128;
    int E = in_sizes[1] / 2;

    float *p_h, *p_agg, *p_hid, *p_Wtl, *p_Wt1, *p_Wt2;
    cudaGetSymbolAddress((void**)&p_h,   g_h);
    cudaGetSymbolAddress((void**)&p_agg, g_agg);
    cudaGetSymbolAddress((void**)&p_hid, g_hid);
    cudaGetSymbolAddress((void**)&p_Wtl, g_Wtl);
    cudaGetSymbolAddress((void**)&p_Wt1, g_Wt1);
    cudaGetSymbolAddress((void**)&p_Wt2, g_Wt2);

    // weight transposes (K-major)
    k_transpose<<<(32768 + 255) / 256, 256>>>(Wl, p_Wtl, 128, 256, 1);
    k_transpose<<<(655360 + 255) / 256, 256>>>(W1, p_Wt1, 256, 512, 5);
    k_transpose<<<(655360 + 255) / 256, 256>>>(W2, p_Wt2, 512, 256, 5);

    // CSR + edge-type counts (layer-invariant)
    int nb512 = (N + 511) / 512;
    k_zero_counts<<<(N + 255) / 256, 256>>>(N);
    k_count<<<(E + 255) / 256, 256>>>(ei, ea, E);
    k_scan1<<<nb512, 512>>>(N);
    k_scan2<<<1, 256>>>(nb512);
    k_scan3<<<nb512, 512>>>(N, nb512);
    k_scatter<<<(E + 255) / 256, 256>>>(ei, E);

    int my = (N + 127) / 128;
    float invN = 1.f / (float)N;

    // h0 = relu(x @ Wl + bl)
    k_gemm_mma<<<dim3(2, my), 256>>>(x, p_Wtl, bl, p_h, N, 128, 256, 8, 1);

    for (int l = 0; l < 5; l++) {
        k_agg<<<(N + 7) / 8, 256>>>(E1 + (size_t)l * 6 * DIM, E2 + (size_t)l * 3 * DIM, N, l > 0);
        k_gemm_mma<<<dim3(4, my), 256>>>(p_agg, p_Wt1 + (size_t)l * HID * DIM,
                                         b1 + (size_t)l * HID, p_hid, N, 256, 512, 16, 1);
        k_gemm_mma<<<dim3(2, my), 256>>>(p_hid, p_Wt2 + (size_t)l * DIM * HID,
                                         b2 + (size_t)l * DIM, p_h, N, 512, 256, 32, 0);
        k_zero_bn<<<1, 256>>>();
        k_bnstats<<<(N + 511) / 512, 256>>>(p_h, N);
        k_bnfin<<<1, 256>>>(gamma + (size_t)l * DIM, beta + (size_t)l * DIM, invN);
    }
    k_bnapply<<<(N * 64 + 255) / 256, 256>>>((float*)d_out, N);
}